// round 15
// baseline (speedup 1.0000x reference)
#include <cuda_runtime.h>
#include <cuda_fp16.h>
#include <cstdint>
#include <cstddef>

#define NN 100000
#define EE 1600000
#define IN_CH 41
#define ED 8
#define HH 64
#define LL 3
#define GG 256
#define ATOM 21
#define EPSN 1e-5f
#define PADT 65
#define SCAN_BLK 512
#define SCAN_NBLK ((NN + SCAN_BLK - 1) / SCAN_BLK)   // 196

// ---------------- scratch (device globals; no allocation) ------------------
static __device__ uint4  g_hh[(size_t)NN * HH / 8];     // normalized h, fp16
static __device__ float4 g_h2buf[(size_t)NN * HH / 4];  // pre-norm h2, fp32
static __device__ float4 g_aggrbuf[(size_t)NN * HH / 4];
static __device__ float  g_SQ[2 * GG * HH];
static __device__ float  g_coef[2 * GG * HH];
static __device__ float  g_cnt[GG];
// CSR
static __device__ int    g_deg[NN];
static __device__ int    g_off[NN + 1];
static __device__ int    g_cur[NN];
static __device__ int    g_bsum[SCAN_NBLK];
static __device__ int    g_csrc[EE];
static __device__ float4 g_eacsr[(size_t)EE * 2];   // ea in CSR order

// ---------------- packed helpers ---------------------------------------------
__device__ __forceinline__ unsigned long long pack2(float lo, float hi) {
    unsigned long long r;
    asm("mov.b64 %0, {%1,%2};" : "=l"(r) : "f"(lo), "f"(hi));
    return r;
}
__device__ __forceinline__ void unpack2(unsigned long long v, float& lo, float& hi) {
    asm("mov.b64 {%0,%1}, %2;" : "=f"(lo), "=f"(hi) : "l"(v));
}
__device__ __forceinline__ void ffma2(unsigned long long& d, unsigned long long a,
                                      unsigned long long b) {
    asm("fma.rn.f32x2 %0, %1, %2, %0;" : "+l"(d) : "l"(a), "l"(b));
}
__device__ __forceinline__ void lds_2u64(unsigned long long& a, unsigned long long& b,
                                         const void* p) {
    unsigned int addr = (unsigned int)__cvta_generic_to_shared(p);
    asm("ld.shared.v2.u64 {%0,%1}, [%2];" : "=l"(a), "=l"(b) : "r"(addr));
}
__device__ __forceinline__ void sts_2u64(void* p, unsigned long long a,
                                         unsigned long long b) {
    unsigned int addr = (unsigned int)__cvta_generic_to_shared(p);
    asm volatile("st.shared.v2.u64 [%0], {%1,%2};" :: "r"(addr), "l"(a), "l"(b));
}
// fp16 pack/unpack
__device__ __forceinline__ unsigned int f2h2(float a, float b) {
    __half2 h = __floats2half2_rn(a, b);
    return *reinterpret_cast<unsigned int*>(&h);
}
__device__ __forceinline__ float2 h2f2(unsigned int u) {
    __half2 h = *reinterpret_cast<__half2*>(&u);
    return __half22float2(h);
}
__device__ __forceinline__ float4 ldh4(const __half* __restrict__ h, int node, int lf) {
    uint2 u = __ldg((const uint2*)(h + (size_t)node * HH + lf));
    float2 a = h2f2(u.x), b = h2f2(u.y);
    return make_float4(a.x, a.y, b.x, b.y);
}

__device__ __forceinline__ int lower_bound_dev(const int* __restrict__ arr, int n, int val) {
    int lo = 0, hi = n;
    while (lo < hi) {
        int mid = (lo + hi) >> 1;
        if (__ldg(&arr[mid]) < val) lo = mid + 1; else hi = mid;
    }
    return lo;
}

// broadcast kstep (encoder)
__device__ __forceinline__ void kstep(const float* __restrict__ wr,
                                      unsigned long long z2,
                                      unsigned long long* __restrict__ acc) {
#pragma unroll
    for (int j = 0; j < 16; j++) {
        unsigned long long w0, w1;
        lds_2u64(w0, w1, wr + j * 4);
        ffma2(acc[2 * j], z2, w0);
        ffma2(acc[2 * j + 1], z2, w1);
    }
}

// per-edge message: relu(hv + ea@We + be) on this thread's 4 features
__device__ __forceinline__ float4 edge_msg(const float4 e0, const float4 e1,
                                           const float4 hv,
                                           const unsigned long long* __restrict__ wreg,
                                           unsigned long long bias0,
                                           unsigned long long bias1) {
    unsigned long long a0 = bias0, a1 = bias1;
#pragma unroll
    for (int k = 0; k < 4; k++) {
        unsigned long long aa = pack2((&e0.x)[k], (&e0.x)[k]);
        ffma2(a0, aa, wreg[2 * k]);
        ffma2(a1, aa, wreg[2 * k + 1]);
    }
#pragma unroll
    for (int k = 0; k < 4; k++) {
        unsigned long long aa = pack2((&e1.x)[k], (&e1.x)[k]);
        ffma2(a0, aa, wreg[8 + 2 * k]);
        ffma2(a1, aa, wreg[8 + 2 * k + 1]);
    }
    float c0, c1, c2, c3;
    unpack2(a0, c0, c1);
    unpack2(a1, c2, c3);
    return make_float4(fmaxf(hv.x + c0, 0.f), fmaxf(hv.y + c1, 0.f),
                       fmaxf(hv.z + c2, 0.f), fmaxf(hv.w + c3, 0.f));
}

// ================= CSR build =================================================
__global__ void __launch_bounds__(256) k_hist(const int* __restrict__ dst,
                                              int* __restrict__ deg)
{
    int e = blockIdx.x * 256 + threadIdx.x;
    if (e < EE) atomicAdd(&deg[__ldg(&dst[e])], 1);
}

__global__ void __launch_bounds__(SCAN_BLK) k_scanblk(const int* __restrict__ deg,
                                                      int* __restrict__ off,
                                                      int* __restrict__ bsum)
{
    __shared__ int sh[SCAN_BLK];
    int tid = threadIdx.x;
    int i = blockIdx.x * SCAN_BLK + tid;
    int v = (i < NN) ? __ldg(&deg[i]) : 0;
    sh[tid] = v;
    __syncthreads();
#pragma unroll
    for (int o = 1; o < SCAN_BLK; o <<= 1) {
        int t = (tid >= o) ? sh[tid - o] : 0;
        __syncthreads();
        sh[tid] += t;
        __syncthreads();
    }
    if (i < NN) off[i] = sh[tid] - v;
    if (tid == SCAN_BLK - 1) bsum[blockIdx.x] = sh[tid];
}

__global__ void k_scantop(int* __restrict__ bsum)
{
    if (threadIdx.x == 0 && blockIdx.x == 0) {
        int run = 0;
        for (int i = 0; i < SCAN_NBLK; i++) {
            int t = bsum[i];
            bsum[i] = run;
            run += t;
        }
    }
}

__global__ void __launch_bounds__(256) k_scanadd(int* __restrict__ off,
                                                 const int* __restrict__ bsum,
                                                 int* __restrict__ cur)
{
    int i = blockIdx.x * 256 + threadIdx.x;
    if (i < NN) {
        int o = off[i] + __ldg(&bsum[i / SCAN_BLK]);
        off[i] = o;
        cur[i] = o;
    }
    if (i == 0) off[NN] = EE;
}

__global__ void __launch_bounds__(256) k_scatter(const int* __restrict__ src,
                                                 const int* __restrict__ dst,
                                                 const float* __restrict__ ea,
                                                 int* __restrict__ cur,
                                                 int* __restrict__ csrc,
                                                 float4* __restrict__ eacsr)
{
    int e = blockIdx.x * 256 + threadIdx.x;
    if (e >= EE) return;
    int d = __ldg(&dst[e]);
    int pos = atomicAdd(&cur[d], 1);
    csrc[pos] = __ldg(&src[e]);
    eacsr[(size_t)pos * 2]     = __ldg((const float4*)(ea + (size_t)e * ED));
    eacsr[(size_t)pos * 2 + 1] = __ldg((const float4*)(ea + (size_t)e * ED) + 1);
}

// ================= gather aggregation: 1 edge/iter, 4 blocks/SM ==============
__global__ void __launch_bounds__(256, 4) k_gather(
    const __half* __restrict__ h,
    const int* __restrict__ off,
    const int* __restrict__ csrc, const float4* __restrict__ eacsr,
    const float* __restrict__ We, const float* __restrict__ be,
    float* __restrict__ aggr)
{
    __shared__ __align__(16) float sW[ED * HH];
    __shared__ __align__(16) float sB[HH];
    for (int i = threadIdx.x; i < ED * HH; i += 256) sW[i] = We[i];
    if (threadIdx.x < HH) sB[threadIdx.x] = be[threadIdx.x];
    __syncthreads();

    const int grp = threadIdx.x >> 4;
    const int lf = (threadIdx.x & 15) * 4;

    unsigned long long wreg[16];
#pragma unroll
    for (int k = 0; k < 8; k++)
        lds_2u64(wreg[2 * k], wreg[2 * k + 1], &sW[k * HH + lf]);
    const unsigned long long bias0 = pack2(sB[lf], sB[lf + 1]);
    const unsigned long long bias1 = pack2(sB[lf + 2], sB[lf + 3]);

    const int n = blockIdx.x * 16 + grp;
    if (n >= NN) return;
    const int beg = __ldg(&off[n]);
    const int end = __ldg(&off[n + 1]);

    float4 accv = make_float4(0.f, 0.f, 0.f, 0.f);

    for (int i = beg; i < end; i++) {
        int s0 = __ldg(&csrc[i]);
        float4 E0a = __ldg(&eacsr[(size_t)i * 2]);
        float4 E0b = __ldg(&eacsr[(size_t)i * 2 + 1]);
        float4 h0 = ldh4(h, s0, lf);
        float4 m0 = edge_msg(E0a, E0b, h0, wreg, bias0, bias1);
        accv.x += m0.x; accv.y += m0.y; accv.z += m0.z; accv.w += m0.w;
    }

    *(float4*)(aggr + (size_t)n * HH + lf) = accv;
}

// ================= fused conv MLP (retiled, fp16 h input) ===================
#define ZP_STRIDE 66
#define MLP_SMEM (64 * ZP_STRIDE * 8 + 4096 * 4 + 128 * 4)  // 50688 B

__global__ void __launch_bounds__(128, 4) k_mlp(
    const __half* __restrict__ hg, const float* __restrict__ ag,
    const float* __restrict__ W1, const float* __restrict__ b1,
    const float* __restrict__ W2, const float* __restrict__ b2,
    float* __restrict__ h2out)
{
    extern __shared__ char smemraw[];
    unsigned long long* zp = (unsigned long long*)smemraw;
    float* sW = (float*)(smemraw + 64 * ZP_STRIDE * 8);
    float* sB = (float*)(smemraw + 64 * ZP_STRIDE * 8 + 16384);

    const int tid = threadIdx.x;
    const int og = tid & 15;
    const int pg = tid >> 4;
    const int n0 = blockIdx.x * 128;

    for (int i = tid; i < 1024; i += 128)
        ((float4*)sW)[i] = __ldg(((const float4*)W1) + i);
    if (tid < HH) { sB[tid] = __ldg(&b1[tid]); sB[64 + tid] = __ldg(&b2[tid]); }

    for (int task = tid; task < 1024; task += 128) {
        int p = task >> 4, q = task & 15;
        int na = n0 + 2 * p;
        int naL = na < NN ? na : NN - 1;
        int nbL = na + 1 < NN ? na + 1 : NN - 1;
        float4 va = ldh4(hg, naL, q * 4);
        float4 vb = ldh4(hg, nbL, q * 4);
        float4 sa = __ldg(((const float4*)ag) + (size_t)naL * 16 + q);
        float4 sb = __ldg(((const float4*)ag) + (size_t)nbL * 16 + q);
        va.x += sa.x; va.y += sa.y; va.z += sa.z; va.w += sa.w;
        vb.x += sb.x; vb.y += sb.y; vb.z += sb.z; vb.w += sb.w;
        int k4 = q * 4;
        zp[(k4 + 0) * ZP_STRIDE + p] = pack2(va.x, vb.x);
        zp[(k4 + 1) * ZP_STRIDE + p] = pack2(va.y, vb.y);
        zp[(k4 + 2) * ZP_STRIDE + p] = pack2(va.z, vb.z);
        zp[(k4 + 3) * ZP_STRIDE + p] = pack2(va.w, vb.w);
    }
    __syncthreads();

    unsigned long long acc[32];
#pragma unroll
    for (int o = 0; o < 4; o++) {
        float bv = sB[og * 4 + o];
        unsigned long long bb = pack2(bv, bv);
#pragma unroll
        for (int j = 0; j < 8; j++) acc[o * 8 + j] = bb;
    }

#pragma unroll 4
    for (int k = 0; k < HH; k++) {
        const unsigned long long* zr = zp + k * ZP_STRIDE + pg * 8;
        unsigned long long z0, z1, z2, z3, z4, z5, z6, z7;
        lds_2u64(z0, z1, zr);     lds_2u64(z2, z3, zr + 2);
        lds_2u64(z4, z5, zr + 4); lds_2u64(z6, z7, zr + 6);
        float4 wv = *(const float4*)(sW + k * HH + og * 4);
#pragma unroll
        for (int o = 0; o < 4; o++) {
            unsigned long long ww = pack2((&wv.x)[o], (&wv.x)[o]);
            ffma2(acc[o * 8 + 0], z0, ww); ffma2(acc[o * 8 + 1], z1, ww);
            ffma2(acc[o * 8 + 2], z2, ww); ffma2(acc[o * 8 + 3], z3, ww);
            ffma2(acc[o * 8 + 4], z4, ww); ffma2(acc[o * 8 + 5], z5, ww);
            ffma2(acc[o * 8 + 6], z6, ww); ffma2(acc[o * 8 + 7], z7, ww);
        }
    }
    __syncthreads();

#pragma unroll
    for (int o = 0; o < 4; o++) {
        unsigned long long* tr = zp + (og * 4 + o) * ZP_STRIDE + pg * 8;
#pragma unroll
        for (int j = 0; j < 8; j += 2) {
            float a0, a1, b0v, b1v;
            unpack2(acc[o * 8 + j], a0, a1);
            unpack2(acc[o * 8 + j + 1], b0v, b1v);
            sts_2u64(tr + j, pack2(fmaxf(a0, 0.f), fmaxf(a1, 0.f)),
                             pack2(fmaxf(b0v, 0.f), fmaxf(b1v, 0.f)));
        }
    }
    for (int i = tid; i < 1024; i += 128)
        ((float4*)sW)[i] = __ldg(((const float4*)W2) + i);
    __syncthreads();

#pragma unroll
    for (int o = 0; o < 4; o++) {
        float bv = sB[64 + og * 4 + o];
        unsigned long long bb = pack2(bv, bv);
#pragma unroll
        for (int j = 0; j < 8; j++) acc[o * 8 + j] = bb;
    }

#pragma unroll 4
    for (int k = 0; k < HH; k++) {
        const unsigned long long* zr = zp + k * ZP_STRIDE + pg * 8;
        unsigned long long z0, z1, z2, z3, z4, z5, z6, z7;
        lds_2u64(z0, z1, zr);     lds_2u64(z2, z3, zr + 2);
        lds_2u64(z4, z5, zr + 4); lds_2u64(z6, z7, zr + 6);
        float4 wv = *(const float4*)(sW + k * HH + og * 4);
#pragma unroll
        for (int o = 0; o < 4; o++) {
            unsigned long long ww = pack2((&wv.x)[o], (&wv.x)[o]);
            ffma2(acc[o * 8 + 0], z0, ww); ffma2(acc[o * 8 + 1], z1, ww);
            ffma2(acc[o * 8 + 2], z2, ww); ffma2(acc[o * 8 + 3], z3, ww);
            ffma2(acc[o * 8 + 4], z4, ww); ffma2(acc[o * 8 + 5], z5, ww);
            ffma2(acc[o * 8 + 6], z6, ww); ffma2(acc[o * 8 + 7], z7, ww);
        }
    }

#pragma unroll
    for (int j = 0; j < 8; j++) {
        int p = pg * 8 + j;
        int ne = n0 + 2 * p, no = ne + 1;
        float e0, d0, e1, d1, e2, d2, e3, d3;
        unpack2(acc[0 * 8 + j], e0, d0);
        unpack2(acc[1 * 8 + j], e1, d1);
        unpack2(acc[2 * 8 + j], e2, d2);
        unpack2(acc[3 * 8 + j], e3, d3);
        if (ne < NN)
            *(float4*)(h2out + (size_t)ne * HH + og * 4) = make_float4(e0, e1, e2, e3);
        if (no < NN)
            *(float4*)(h2out + (size_t)no * HH + og * 4) = make_float4(d0, d1, d2, d3);
    }
}

// ================= fused encoder (dual branch, fp16 output) =================
#define ENC_SMEM ((8192 + 128 * PADT + 256) * 4)

__global__ void __launch_bounds__(128, 3) k_encoder(
    const float* __restrict__ x,
    const float* __restrict__ lW1, const float* __restrict__ lb1,
    const float* __restrict__ lW2, const float* __restrict__ lb2,
    const float* __restrict__ pW1, const float* __restrict__ pb1,
    const float* __restrict__ pW2, const float* __restrict__ pb2,
    __half* __restrict__ hout)
{
    extern __shared__ float smem[];
    float* sWreg = smem;
    float* sT    = smem + 8192;
    float* sB    = smem + 8192 + 128 * PADT;

    const int tid = threadIdx.x;
    const int n0 = blockIdx.x * 128;
    const int node = n0 + tid;
    const bool valid = node < NN;

    float* sWl1 = sWreg;
    float* sWp1 = sWreg + 2624;
    for (int i = tid; i < 656; i += 128) {
        ((float4*)sWl1)[i] = __ldg(((const float4*)lW1) + i);
        ((float4*)sWp1)[i] = __ldg(((const float4*)pW1) + i);
    }
    if (tid < HH) {
        sB[tid] = __ldg(&lb1[tid]); sB[64 + tid] = __ldg(&pb1[tid]);
        sB[128 + tid] = __ldg(&lb2[tid]); sB[192 + tid] = __ldg(&pb2[tid]);
    }
    for (int c = tid; c < 128 * IN_CH; c += 128) {
        int n = c / IN_CH, k = c - n * IN_CH;
        sT[n * PADT + k] = (n0 + n < NN) ? __ldg(&x[(size_t)(n0 + n) * IN_CH + k]) : 0.f;
    }
    __syncthreads();

    float* trow = sT + tid * PADT;
    float s = 0.f;
#pragma unroll
    for (int k = ATOM; k < IN_CH; k++) s += fabsf(trow[k]);
    const bool prot = s > 1e-6f;
    const float* sW1 = prot ? sWp1 : sWl1;
    const float* b1 = prot ? (sB + 64) : sB;
    const float* b2 = prot ? (sB + 192) : (sB + 128);

    unsigned long long acc[32];
#pragma unroll
    for (int j = 0; j < 32; j++) acc[j] = pack2(b1[2 * j], b1[2 * j + 1]);
    for (int k = 0; k < IN_CH; k++) {
        float zv = trow[k];
        kstep(sW1 + k * HH, pack2(zv, zv), acc);
    }
    float tv[HH];
#pragma unroll
    for (int j = 0; j < 32; j++) {
        float lo, hi; unpack2(acc[j], lo, hi);
        tv[2 * j] = fmaxf(lo, 0.f);
        tv[2 * j + 1] = fmaxf(hi, 0.f);
    }
    __syncthreads();

    float* sWl2 = sWreg;
    float* sWp2 = sWreg + 4096;
    for (int i = tid; i < 1024; i += 128) {
        ((float4*)sWl2)[i] = __ldg(((const float4*)lW2) + i);
        ((float4*)sWp2)[i] = __ldg(((const float4*)pW2) + i);
    }
#pragma unroll
    for (int j = 0; j < HH; j++) trow[j] = tv[j];
    __syncthreads();

    const float* sW2 = prot ? sWp2 : sWl2;
#pragma unroll
    for (int j = 0; j < 32; j++) acc[j] = pack2(b2[2 * j], b2[2 * j + 1]);
    for (int k = 0; k < HH; k++) {
        float zv = trow[k];
        kstep(sW2 + k * HH, pack2(zv, zv), acc);
    }
    if (valid) {
        uint4* op = (uint4*)(hout + (size_t)node * HH);
#pragma unroll
        for (int q = 0; q < 8; q++) {
            float f[8];
#pragma unroll
            for (int j = 0; j < 4; j++) {
                float lo, hi;
                unpack2(acc[q * 4 + j], lo, hi);
                f[2 * j] = fmaxf(lo, 0.f);
                f[2 * j + 1] = fmaxf(hi, 0.f);
            }
            uint4 v;
            v.x = f2h2(f[0], f[1]);
            v.y = f2h2(f[2], f[3]);
            v.z = f2h2(f[4], f[5]);
            v.w = f2h2(f[6], f[7]);
            op[q] = v;
        }
    }
}

// ================= GraphNorm: chunked stats -> S,Q ==========================
__global__ void __launch_bounds__(256) k_stats(
    const float* __restrict__ h2, const int* __restrict__ batch,
    float* __restrict__ SQ)
{
    const int c0 = blockIdx.x * 256;
    const int cend = (c0 + 256 < NN) ? c0 + 256 : NN;
    const int tid = threadIdx.x;
    const int f = tid & 63;
    const int slot = tid >> 6;

    const int g0 = __ldg(&batch[c0]);
    const int g1 = __ldg(&batch[cend - 1]);
    const int span = g1 - g0 + 1;

    __shared__ float sS[8 * 64], sQ[8 * 64];
    if (span <= 8) {
        for (int i = tid; i < 512; i += 256) { sS[i] = 0.f; sQ[i] = 0.f; }
        __syncthreads();
        for (int i = c0 + slot; i < cend; i += 4) {
            float v = __ldg(&h2[(size_t)i * HH + f]);
            int gi = __ldg(&batch[i]) - g0;
            atomicAdd(&sS[gi * 64 + f], v);
            atomicAdd(&sQ[gi * 64 + f], v * v);
        }
        __syncthreads();
        for (int i2 = tid; i2 < span * 64; i2 += 256) {
            int gg = g0 + (i2 >> 6);
            atomicAdd(&SQ[gg * 64 + (i2 & 63)], sS[i2]);
            atomicAdd(&SQ[GG * HH + gg * 64 + (i2 & 63)], sQ[i2]);
        }
    } else {
        for (int i = c0 + slot; i < cend; i += 4) {
            float v = __ldg(&h2[(size_t)i * HH + f]);
            int gg = __ldg(&batch[i]);
            atomicAdd(&SQ[gg * 64 + f], v);
            atomicAdd(&SQ[GG * HH + gg * 64 + f], v * v);
        }
    }
}

__global__ void k_counts(const int* __restrict__ batch, float* __restrict__ cnt)
{
    int g = blockIdx.x * blockDim.x + threadIdx.x;
    if (g >= GG) return;
    int a = lower_bound_dev(batch, NN, g);
    int b = lower_bound_dev(batch, NN, g + 1);
    int c = b - a;
    cnt[g] = (float)(c > 0 ? c : 1);
}

__global__ void __launch_bounds__(256) k_coef(
    const float* __restrict__ SQ, const float* __restrict__ cnt,
    const float* __restrict__ w, const float* __restrict__ b,
    const float* __restrict__ alpha, float* __restrict__ coef)
{
    int idx = blockIdx.x * 256 + threadIdx.x;
    int g = idx >> 6, f = idx & 63;
    float c = __ldg(&cnt[g]);
    float S = __ldg(&SQ[idx]);
    float Q = __ldg(&SQ[GG * HH + idx]);
    float m = S / c;
    float m2 = Q / c;
    float a = __ldg(&alpha[f]);
    float var = m2 - m * m * a * (2.0f - a);
    float rstd = rsqrtf(var + EPSN);
    float wf = __ldg(&w[f]);
    coef[idx] = wf * rstd;
    coef[GG * HH + idx] = __ldg(&b[f]) - wf * rstd * a * m;
}

// apply + relu, write fp16
__global__ void __launch_bounds__(256) k_apply(
    const float* __restrict__ h2, const int* __restrict__ batch,
    const float* __restrict__ coef, __half* __restrict__ hout)
{
    int idx = blockIdx.x * 256 + threadIdx.x;
    if (idx >= NN * 16) return;
    int node = idx >> 4, q = idx & 15;
    int g = __ldg(&batch[node]);
    float4 v = __ldg(((const float4*)h2) + idx);
    float4 c1 = __ldg(((const float4*)coef) + g * 16 + q);
    float4 c2 = __ldg(((const float4*)(coef + GG * HH)) + g * 16 + q);
    float o0 = fmaxf(fmaf(c1.x, v.x, c2.x), 0.f);
    float o1 = fmaxf(fmaf(c1.y, v.y, c2.y), 0.f);
    float o2 = fmaxf(fmaf(c1.z, v.z, c2.z), 0.f);
    float o3 = fmaxf(fmaf(c1.w, v.w, c2.w), 0.f);
    uint2 u;
    u.x = f2h2(o0, o1);
    u.y = f2h2(o2, o3);
    *(uint2*)(hout + (size_t)node * HH + q * 4) = u;
}

__global__ void __launch_bounds__(128) k_readout(
    const __half* __restrict__ h, const int* __restrict__ batch,
    const float* __restrict__ W1, const float* __restrict__ b1,
    const float* __restrict__ W2, const float* __restrict__ b2,
    float* __restrict__ out)
{
    const int g = blockIdx.x;
    const int tid = threadIdx.x;
    __shared__ int sRange[2];
    if (tid < 2) sRange[tid] = lower_bound_dev(batch, NN, g + tid);
    __syncthreads();
    const int start = sRange[0], end = sRange[1];

    const int f2 = (tid & 31) * 2;
    const int slot = tid >> 5;
    float s0 = 0.f, s1 = 0.f;
    for (int i = start + slot; i < end; i += 4) {
        unsigned int u = __ldg((const unsigned int*)(h + (size_t)i * HH + f2));
        float2 v = h2f2(u);
        s0 += v.x; s1 += v.y;
    }

    __shared__ float sp[256];
    __shared__ float pool[HH];
    __shared__ float tvs[HH];
    sp[tid * 2] = s0;
    sp[tid * 2 + 1] = s1;
    __syncthreads();
    if (tid < HH) {
        float acc = 0.f;
#pragma unroll
        for (int sl = 0; sl < 4; sl++)
            acc += sp[(sl * 32 + (tid >> 1)) * 2 + (tid & 1)];
        pool[tid] = acc;
    }
    __syncthreads();
    if (tid < HH) {
        float acc = __ldg(&b1[tid]);
#pragma unroll
        for (int k = 0; k < HH; k++)
            acc = fmaf(pool[k], __ldg(&W1[k * HH + tid]), acc);
        tvs[tid] = fmaxf(acc, 0.f) * __ldg(&W2[tid]);
    }
    __syncthreads();
    if (tid == 0) {
        float r = __ldg(b2);
#pragma unroll
        for (int k = 0; k < HH; k++) r += tvs[k];
        out[g] = r;
    }
}

// ================= launch ====================================================
extern "C" void kernel_launch(void* const* d_in, const int* in_sizes, int n_in,
                              void* d_out, int out_size)
{
    const float* x       = (const float*)d_in[0];
    const int*   ei      = (const int*)d_in[1];
    const float* ea      = (const float*)d_in[2];
    const int*   batch   = (const int*)d_in[3];
    const float* lig_W1  = (const float*)d_in[4];
    const float* lig_b1  = (const float*)d_in[5];
    const float* lig_W2  = (const float*)d_in[6];
    const float* lig_b2  = (const float*)d_in[7];
    const float* prot_W1 = (const float*)d_in[8];
    const float* prot_b1 = (const float*)d_in[9];
    const float* prot_W2 = (const float*)d_in[10];
    const float* prot_b2 = (const float*)d_in[11];
    const float* conv_We = (const float*)d_in[12];
    const float* conv_be = (const float*)d_in[13];
    const float* conv_W1 = (const float*)d_in[14];
    const float* conv_b1 = (const float*)d_in[15];
    const float* conv_W2 = (const float*)d_in[16];
    const float* conv_b2 = (const float*)d_in[17];
    const float* norm_w  = (const float*)d_in[18];
    const float* norm_b  = (const float*)d_in[19];
    const float* norm_a  = (const float*)d_in[20];
    const float* out_W1  = (const float*)d_in[21];
    const float* out_b1  = (const float*)d_in[22];
    const float* out_W2  = (const float*)d_in[23];
    const float* out_b2  = (const float*)d_in[24];
    float* out = (float*)d_out;

    const int* src = ei;
    const int* dst = ei + EE;

    void *phh, *ph2, *pag, *psq, *pcoef, *pcnt;
    void *pdeg, *poff, *pcur, *pbsum, *pcsrc, *peacsr;
    cudaGetSymbolAddress(&phh,  g_hh);
    cudaGetSymbolAddress(&ph2,  g_h2buf);
    cudaGetSymbolAddress(&pag,  g_aggrbuf);
    cudaGetSymbolAddress(&psq,  g_SQ);
    cudaGetSymbolAddress(&pcoef, g_coef);
    cudaGetSymbolAddress(&pcnt, g_cnt);
    cudaGetSymbolAddress(&pdeg, g_deg);
    cudaGetSymbolAddress(&poff, g_off);
    cudaGetSymbolAddress(&pcur, g_cur);
    cudaGetSymbolAddress(&pbsum, g_bsum);
    cudaGetSymbolAddress(&pcsrc, g_csrc);
    cudaGetSymbolAddress(&peacsr, g_eacsr);
    __half* h   = (__half*)phh;
    float* h2   = (float*)ph2;
    float* aggr = (float*)pag;
    float* SQ   = (float*)psq;
    float* coef = (float*)pcoef;
    float* cnt  = (float*)pcnt;
    int* deg  = (int*)pdeg;
    int* off  = (int*)poff;
    int* cur  = (int*)pcur;
    int* bsum = (int*)pbsum;
    int* csrc = (int*)pcsrc;
    float4* eacsr = (float4*)peacsr;

    static cudaStream_t s2 = nullptr;
    static cudaEvent_t evFork = nullptr, evJoin = nullptr;
    static bool attr_done = false;
    if (!attr_done) {
        cudaFuncSetAttribute(k_mlp, cudaFuncAttributeMaxDynamicSharedMemorySize, MLP_SMEM);
        cudaFuncSetAttribute(k_encoder, cudaFuncAttributeMaxDynamicSharedMemorySize, ENC_SMEM);
        cudaStreamCreateWithFlags(&s2, cudaStreamNonBlocking);
        cudaEventCreateWithFlags(&evFork, cudaEventDisableTiming);
        cudaEventCreateWithFlags(&evJoin, cudaEventDisableTiming);
        attr_done = true;
    }

    const int nodeBlocks = (NN + 127) / 128;        // 782
    const int gatherBlocks = (NN + 15) / 16;        // 6250
    const int edgeThreadBlocks = (EE + 255) / 256;  // 6250
    const int applyBlocks = (NN * 16 + 255) / 256;

    // ---- fork: CSR build on s2, encoder on main stream, concurrently ----
    cudaEventRecord(evFork, 0);
    cudaStreamWaitEvent(s2, evFork, 0);

    cudaMemsetAsync(deg, 0, NN * sizeof(int), s2);
    k_hist<<<edgeThreadBlocks, 256, 0, s2>>>(dst, deg);
    k_scanblk<<<SCAN_NBLK, SCAN_BLK, 0, s2>>>(deg, off, bsum);
    k_scantop<<<1, 32, 0, s2>>>(bsum);
    k_scanadd<<<(NN + 255) / 256, 256, 0, s2>>>(off, bsum, cur);
    k_scatter<<<edgeThreadBlocks, 256, 0, s2>>>(src, dst, ea, cur, csrc, eacsr);
    cudaEventRecord(evJoin, s2);

    k_counts<<<1, 256>>>(batch, cnt);
    k_encoder<<<nodeBlocks, 128, ENC_SMEM>>>(x, lig_W1, lig_b1, lig_W2, lig_b2,
                                             prot_W1, prot_b1, prot_W2, prot_b2, h);

    cudaStreamWaitEvent(0, evJoin, 0);

    for (int l = 0; l < LL; l++) {
        k_gather<<<gatherBlocks, 256>>>(h, off, csrc, eacsr,
                                        conv_We + l * ED * HH, conv_be + l * HH, aggr);
        k_mlp<<<nodeBlocks, 128, MLP_SMEM>>>(h, aggr,
                                             conv_W1 + l * HH * HH, conv_b1 + l * HH,
                                             conv_W2 + l * HH * HH, conv_b2 + l * HH,
                                             h2);
        cudaMemsetAsync(SQ, 0, 2 * GG * HH * sizeof(float));
        k_stats<<<(NN + 255) / 256, 256>>>(h2, batch, SQ);
        k_coef<<<GG * HH / 256, 256>>>(SQ, cnt, norm_w + l * HH, norm_b + l * HH,
                                       norm_a + l * HH, coef);
        k_apply<<<applyBlocks, 256>>>(h2, batch, coef, h);
    }

    k_readout<<<GG, 128>>>(h, batch, out_W1, out_b1, out_W2, out_b2, out);
}

// round 16
// speedup vs baseline: 1.1059x; 1.1059x over previous
#include <cuda_runtime.h>
#include <cuda_fp16.h>
#include <cstdint>
#include <cstddef>

#define NN 100000
#define EE 1600000
#define IN_CH 41
#define ED 8
#define HH 64
#define LL 3
#define GG 256
#define ATOM 21
#define EPSN 1e-5f
#define PADT 65
#define SCAN_BLK 512
#define SCAN_NBLK ((NN + SCAN_BLK - 1) / SCAN_BLK)   // 196

// ---------------- scratch (device globals; no allocation) ------------------
static __device__ uint4  g_hh[(size_t)NN * HH / 8];     // normalized h, fp16
static __device__ float4 g_h2buf[(size_t)NN * HH / 4];  // pre-norm h2, fp32
static __device__ float4 g_aggrbuf[(size_t)NN * HH / 4];
static __device__ float  g_SQ[2 * GG * HH];             // zero-init; coef re-zeroes
static __device__ float  g_coef[2 * GG * HH];
static __device__ float  g_cnt[GG];
// CSR
static __device__ int    g_deg[NN];
static __device__ int    g_off[NN + 1];
static __device__ int    g_cur[NN];
static __device__ int    g_bsum[SCAN_NBLK];
static __device__ int    g_csrc[EE];
static __device__ float4 g_eacsr[(size_t)EE * 2];

// ---------------- packed helpers ---------------------------------------------
__device__ __forceinline__ unsigned long long pack2(float lo, float hi) {
    unsigned long long r;
    asm("mov.b64 %0, {%1,%2};" : "=l"(r) : "f"(lo), "f"(hi));
    return r;
}
__device__ __forceinline__ void unpack2(unsigned long long v, float& lo, float& hi) {
    asm("mov.b64 {%0,%1}, %2;" : "=f"(lo), "=f"(hi) : "l"(v));
}
__device__ __forceinline__ void ffma2(unsigned long long& d, unsigned long long a,
                                      unsigned long long b) {
    asm("fma.rn.f32x2 %0, %1, %2, %0;" : "+l"(d) : "l"(a), "l"(b));
}
__device__ __forceinline__ void lds_2u64(unsigned long long& a, unsigned long long& b,
                                         const void* p) {
    unsigned int addr = (unsigned int)__cvta_generic_to_shared(p);
    asm("ld.shared.v2.u64 {%0,%1}, [%2];" : "=l"(a), "=l"(b) : "r"(addr));
}
__device__ __forceinline__ void sts_2u64(void* p, unsigned long long a,
                                         unsigned long long b) {
    unsigned int addr = (unsigned int)__cvta_generic_to_shared(p);
    asm volatile("st.shared.v2.u64 [%0], {%1,%2};" :: "r"(addr), "l"(a), "l"(b));
}
__device__ __forceinline__ unsigned int f2h2(float a, float b) {
    __half2 h = __floats2half2_rn(a, b);
    return *reinterpret_cast<unsigned int*>(&h);
}
__device__ __forceinline__ float2 h2f2(unsigned int u) {
    __half2 h = *reinterpret_cast<__half2*>(&u);
    return __half22float2(h);
}
__device__ __forceinline__ float4 ldh4(const __half* __restrict__ h, int node, int lf) {
    uint2 u = __ldg((const uint2*)(h + (size_t)node * HH + lf));
    float2 a = h2f2(u.x), b = h2f2(u.y);
    return make_float4(a.x, a.y, b.x, b.y);
}

__device__ __forceinline__ int lower_bound_dev(const int* __restrict__ arr, int n, int val) {
    int lo = 0, hi = n;
    while (lo < hi) {
        int mid = (lo + hi) >> 1;
        if (__ldg(&arr[mid]) < val) lo = mid + 1; else hi = mid;
    }
    return lo;
}

// broadcast kstep (encoder)
__device__ __forceinline__ void kstep(const float* __restrict__ wr,
                                      unsigned long long z2,
                                      unsigned long long* __restrict__ acc) {
#pragma unroll
    for (int j = 0; j < 16; j++) {
        unsigned long long w0, w1;
        lds_2u64(w0, w1, wr + j * 4);
        ffma2(acc[2 * j], z2, w0);
        ffma2(acc[2 * j + 1], z2, w1);
    }
}

// per-edge message: relu(hv + ea@We + be) on this thread's 4 features
__device__ __forceinline__ float4 edge_msg(const float4 e0, const float4 e1,
                                           const float4 hv,
                                           const unsigned long long* __restrict__ wreg,
                                           unsigned long long bias0,
                                           unsigned long long bias1) {
    unsigned long long a0 = bias0, a1 = bias1;
#pragma unroll
    for (int k = 0; k < 4; k++) {
        unsigned long long aa = pack2((&e0.x)[k], (&e0.x)[k]);
        ffma2(a0, aa, wreg[2 * k]);
        ffma2(a1, aa, wreg[2 * k + 1]);
    }
#pragma unroll
    for (int k = 0; k < 4; k++) {
        unsigned long long aa = pack2((&e1.x)[k], (&e1.x)[k]);
        ffma2(a0, aa, wreg[8 + 2 * k]);
        ffma2(a1, aa, wreg[8 + 2 * k + 1]);
    }
    float c0, c1, c2, c3;
    unpack2(a0, c0, c1);
    unpack2(a1, c2, c3);
    return make_float4(fmaxf(hv.x + c0, 0.f), fmaxf(hv.y + c1, 0.f),
                       fmaxf(hv.z + c2, 0.f), fmaxf(hv.w + c3, 0.f));
}

// ================= CSR build =================================================
__global__ void __launch_bounds__(256) k_hist(const int* __restrict__ dst,
                                              int* __restrict__ deg)
{
    int e = blockIdx.x * 256 + threadIdx.x;
    if (e < EE) atomicAdd(&deg[__ldg(&dst[e])], 1);
}

__global__ void __launch_bounds__(SCAN_BLK) k_scanblk(const int* __restrict__ deg,
                                                      int* __restrict__ off,
                                                      int* __restrict__ bsum)
{
    __shared__ int sh[SCAN_BLK];
    int tid = threadIdx.x;
    int i = blockIdx.x * SCAN_BLK + tid;
    int v = (i < NN) ? __ldg(&deg[i]) : 0;
    sh[tid] = v;
    __syncthreads();
#pragma unroll
    for (int o = 1; o < SCAN_BLK; o <<= 1) {
        int t = (tid >= o) ? sh[tid - o] : 0;
        __syncthreads();
        sh[tid] += t;
        __syncthreads();
    }
    if (i < NN) off[i] = sh[tid] - v;
    if (tid == SCAN_BLK - 1) bsum[blockIdx.x] = sh[tid];
}

__global__ void k_scantop(int* __restrict__ bsum)
{
    if (threadIdx.x == 0 && blockIdx.x == 0) {
        int run = 0;
        for (int i = 0; i < SCAN_NBLK; i++) {
            int t = bsum[i];
            bsum[i] = run;
            run += t;
        }
    }
}

__global__ void __launch_bounds__(256) k_scanadd(int* __restrict__ off,
                                                 const int* __restrict__ bsum,
                                                 int* __restrict__ cur)
{
    int i = blockIdx.x * 256 + threadIdx.x;
    if (i < NN) {
        int o = off[i] + __ldg(&bsum[i / SCAN_BLK]);
        off[i] = o;
        cur[i] = o;
    }
    if (i == 0) off[NN] = EE;
}

__global__ void __launch_bounds__(256) k_scatter(const int* __restrict__ src,
                                                 const int* __restrict__ dst,
                                                 const float* __restrict__ ea,
                                                 int* __restrict__ cur,
                                                 int* __restrict__ csrc,
                                                 float4* __restrict__ eacsr)
{
    int e = blockIdx.x * 256 + threadIdx.x;
    if (e >= EE) return;
    int d = __ldg(&dst[e]);
    int pos = atomicAdd(&cur[d], 1);
    csrc[pos] = __ldg(&src[e]);
    eacsr[(size_t)pos * 2]     = __ldg((const float4*)(ea + (size_t)e * ED));
    eacsr[(size_t)pos * 2 + 1] = __ldg((const float4*)(ea + (size_t)e * ED) + 1);
}

// ================= gather: R14 config (2 edges/iter, 3 blocks/SM) ============
__global__ void __launch_bounds__(256, 3) k_gather(
    const __half* __restrict__ h,
    const int* __restrict__ off,
    const int* __restrict__ csrc, const float4* __restrict__ eacsr,
    const float* __restrict__ We, const float* __restrict__ be,
    float* __restrict__ aggr)
{
    __shared__ __align__(16) float sW[ED * HH];
    __shared__ __align__(16) float sB[HH];
    for (int i = threadIdx.x; i < ED * HH; i += 256) sW[i] = We[i];
    if (threadIdx.x < HH) sB[threadIdx.x] = be[threadIdx.x];
    __syncthreads();

    const int grp = threadIdx.x >> 4;
    const int lf = (threadIdx.x & 15) * 4;

    unsigned long long wreg[16];
#pragma unroll
    for (int k = 0; k < 8; k++)
        lds_2u64(wreg[2 * k], wreg[2 * k + 1], &sW[k * HH + lf]);
    const unsigned long long bias0 = pack2(sB[lf], sB[lf + 1]);
    const unsigned long long bias1 = pack2(sB[lf + 2], sB[lf + 3]);

    const int n = blockIdx.x * 16 + grp;
    if (n >= NN) return;
    const int beg = __ldg(&off[n]);
    const int end = __ldg(&off[n + 1]);

    float4 accv = make_float4(0.f, 0.f, 0.f, 0.f);

    int i = beg;
    for (; i + 2 <= end; i += 2) {
        int s0 = __ldg(&csrc[i]);
        int s1 = __ldg(&csrc[i + 1]);
        float4 E0a = __ldg(&eacsr[(size_t)i * 2]);
        float4 E0b = __ldg(&eacsr[(size_t)i * 2 + 1]);
        float4 E1a = __ldg(&eacsr[(size_t)(i + 1) * 2]);
        float4 E1b = __ldg(&eacsr[(size_t)(i + 1) * 2 + 1]);
        float4 h0 = ldh4(h, s0, lf);
        float4 h1 = ldh4(h, s1, lf);

        float4 m0 = edge_msg(E0a, E0b, h0, wreg, bias0, bias1);
        float4 m1 = edge_msg(E1a, E1b, h1, wreg, bias0, bias1);
        accv.x += m0.x + m1.x;
        accv.y += m0.y + m1.y;
        accv.z += m0.z + m1.z;
        accv.w += m0.w + m1.w;
    }
    if (i < end) {
        int s0 = __ldg(&csrc[i]);
        float4 E0a = __ldg(&eacsr[(size_t)i * 2]);
        float4 E0b = __ldg(&eacsr[(size_t)i * 2 + 1]);
        float4 h0 = ldh4(h, s0, lf);
        float4 m0 = edge_msg(E0a, E0b, h0, wreg, bias0, bias1);
        accv.x += m0.x; accv.y += m0.y; accv.z += m0.z; accv.w += m0.w;
    }

    *(float4*)(aggr + (size_t)n * HH + lf) = accv;
}

// ================= fused conv MLP + GraphNorm stats =========================
#define ZP_STRIDE 66
#define MLP_SMEM (64 * ZP_STRIDE * 8 + 4096 * 4 + 128 * 4)  // 50688 B

__global__ void __launch_bounds__(128, 4) k_mlp(
    const __half* __restrict__ hg, const float* __restrict__ ag,
    const int* __restrict__ batch,
    const float* __restrict__ W1, const float* __restrict__ b1,
    const float* __restrict__ W2, const float* __restrict__ b2,
    float* __restrict__ h2out, float* __restrict__ SQ)
{
    extern __shared__ char smemraw[];
    unsigned long long* zp = (unsigned long long*)smemraw;
    float* sW = (float*)(smemraw + 64 * ZP_STRIDE * 8);
    float* sB = (float*)(smemraw + 64 * ZP_STRIDE * 8 + 16384);

    const int tid = threadIdx.x;
    const int og = tid & 15;
    const int pg = tid >> 4;
    const int n0 = blockIdx.x * 128;

    for (int i = tid; i < 1024; i += 128)
        ((float4*)sW)[i] = __ldg(((const float4*)W1) + i);
    if (tid < HH) { sB[tid] = __ldg(&b1[tid]); sB[64 + tid] = __ldg(&b2[tid]); }

    for (int task = tid; task < 1024; task += 128) {
        int p = task >> 4, q = task & 15;
        int na = n0 + 2 * p;
        int naL = na < NN ? na : NN - 1;
        int nbL = na + 1 < NN ? na + 1 : NN - 1;
        float4 va = ldh4(hg, naL, q * 4);
        float4 vb = ldh4(hg, nbL, q * 4);
        float4 sa = __ldg(((const float4*)ag) + (size_t)naL * 16 + q);
        float4 sb = __ldg(((const float4*)ag) + (size_t)nbL * 16 + q);
        va.x += sa.x; va.y += sa.y; va.z += sa.z; va.w += sa.w;
        vb.x += sb.x; vb.y += sb.y; vb.z += sb.z; vb.w += sb.w;
        int k4 = q * 4;
        zp[(k4 + 0) * ZP_STRIDE + p] = pack2(va.x, vb.x);
        zp[(k4 + 1) * ZP_STRIDE + p] = pack2(va.y, vb.y);
        zp[(k4 + 2) * ZP_STRIDE + p] = pack2(va.z, vb.z);
        zp[(k4 + 3) * ZP_STRIDE + p] = pack2(va.w, vb.w);
    }
    __syncthreads();

    unsigned long long acc[32];
#pragma unroll
    for (int o = 0; o < 4; o++) {
        float bv = sB[og * 4 + o];
        unsigned long long bb = pack2(bv, bv);
#pragma unroll
        for (int j = 0; j < 8; j++) acc[o * 8 + j] = bb;
    }

#pragma unroll 4
    for (int k = 0; k < HH; k++) {
        const unsigned long long* zr = zp + k * ZP_STRIDE + pg * 8;
        unsigned long long z0, z1, z2, z3, z4, z5, z6, z7;
        lds_2u64(z0, z1, zr);     lds_2u64(z2, z3, zr + 2);
        lds_2u64(z4, z5, zr + 4); lds_2u64(z6, z7, zr + 6);
        float4 wv = *(const float4*)(sW + k * HH + og * 4);
#pragma unroll
        for (int o = 0; o < 4; o++) {
            unsigned long long ww = pack2((&wv.x)[o], (&wv.x)[o]);
            ffma2(acc[o * 8 + 0], z0, ww); ffma2(acc[o * 8 + 1], z1, ww);
            ffma2(acc[o * 8 + 2], z2, ww); ffma2(acc[o * 8 + 3], z3, ww);
            ffma2(acc[o * 8 + 4], z4, ww); ffma2(acc[o * 8 + 5], z5, ww);
            ffma2(acc[o * 8 + 6], z6, ww); ffma2(acc[o * 8 + 7], z7, ww);
        }
    }
    __syncthreads();

#pragma unroll
    for (int o = 0; o < 4; o++) {
        unsigned long long* tr = zp + (og * 4 + o) * ZP_STRIDE + pg * 8;
#pragma unroll
        for (int j = 0; j < 8; j += 2) {
            float a0, a1, b0v, b1v;
            unpack2(acc[o * 8 + j], a0, a1);
            unpack2(acc[o * 8 + j + 1], b0v, b1v);
            sts_2u64(tr + j, pack2(fmaxf(a0, 0.f), fmaxf(a1, 0.f)),
                             pack2(fmaxf(b0v, 0.f), fmaxf(b1v, 0.f)));
        }
    }
    for (int i = tid; i < 1024; i += 128)
        ((float4*)sW)[i] = __ldg(((const float4*)W2) + i);
    __syncthreads();

#pragma unroll
    for (int o = 0; o < 4; o++) {
        float bv = sB[64 + og * 4 + o];
        unsigned long long bb = pack2(bv, bv);
#pragma unroll
        for (int j = 0; j < 8; j++) acc[o * 8 + j] = bb;
    }

#pragma unroll 4
    for (int k = 0; k < HH; k++) {
        const unsigned long long* zr = zp + k * ZP_STRIDE + pg * 8;
        unsigned long long z0, z1, z2, z3, z4, z5, z6, z7;
        lds_2u64(z0, z1, zr);     lds_2u64(z2, z3, zr + 2);
        lds_2u64(z4, z5, zr + 4); lds_2u64(z6, z7, zr + 6);
        float4 wv = *(const float4*)(sW + k * HH + og * 4);
#pragma unroll
        for (int o = 0; o < 4; o++) {
            unsigned long long ww = pack2((&wv.x)[o], (&wv.x)[o]);
            ffma2(acc[o * 8 + 0], z0, ww); ffma2(acc[o * 8 + 1], z1, ww);
            ffma2(acc[o * 8 + 2], z2, ww); ffma2(acc[o * 8 + 3], z3, ww);
            ffma2(acc[o * 8 + 4], z4, ww); ffma2(acc[o * 8 + 5], z5, ww);
            ffma2(acc[o * 8 + 6], z6, ww); ffma2(acc[o * 8 + 7], z7, ww);
        }
    }

    // store h2
#pragma unroll
    for (int j = 0; j < 8; j++) {
        int p = pg * 8 + j;
        int ne = n0 + 2 * p, no = ne + 1;
        float e0, d0, e1, d1, e2, d2, e3, d3;
        unpack2(acc[0 * 8 + j], e0, d0);
        unpack2(acc[1 * 8 + j], e1, d1);
        unpack2(acc[2 * 8 + j], e2, d2);
        unpack2(acc[3 * 8 + j], e3, d3);
        if (ne < NN)
            *(float4*)(h2out + (size_t)ne * HH + og * 4) = make_float4(e0, e1, e2, e3);
        if (no < NN)
            *(float4*)(h2out + (size_t)no * HH + og * 4) = make_float4(d0, d1, d2, d3);
    }

    // ---- fused GraphNorm stats (reuse zp region; all zp reads are done) ----
    __syncthreads();
    float* sS = (float*)smemraw;             // 8*64
    float* sQ = sS + 512;                    // 8*64
    int*   sGid = (int*)(sQ + 512);          // 128

    const int nEnd = (n0 + 128 < NN) ? n0 + 128 : NN;
    if (tid < 128) {
        int nn = n0 + tid;
        sGid[tid] = __ldg(&batch[nn < NN ? nn : NN - 1]);
    }
    __syncthreads();
    const int g0 = sGid[0];
    const int g1 = sGid[nEnd - 1 - n0];
    const int span = g1 - g0 + 1;

    if (span <= 8) {
        for (int i = tid; i < 1024; i += 128) sS[i] = 0.f;  // covers sS+sQ
        __syncthreads();
#pragma unroll
        for (int j = 0; j < 8; j++) {
            int p = pg * 8 + j;
            int ne = n0 + 2 * p, no = ne + 1;
#pragma unroll
            for (int o = 0; o < 4; o++) {
                int f = og * 4 + o;
                float ev, dv;
                unpack2(acc[o * 8 + j], ev, dv);
                if (ne < NN) {
                    int gi = sGid[2 * p] - g0;
                    atomicAdd(&sS[gi * 64 + f], ev);
                    atomicAdd(&sQ[gi * 64 + f], ev * ev);
                }
                if (no < NN) {
                    int gi = sGid[2 * p + 1] - g0;
                    atomicAdd(&sS[gi * 64 + f], dv);
                    atomicAdd(&sQ[gi * 64 + f], dv * dv);
                }
            }
        }
        __syncthreads();
        for (int i2 = tid; i2 < span * 64; i2 += 128) {
            int gg = g0 + (i2 >> 6);
            atomicAdd(&SQ[gg * 64 + (i2 & 63)], sS[i2]);
            atomicAdd(&SQ[GG * HH + gg * 64 + (i2 & 63)], sQ[i2]);
        }
    } else {
#pragma unroll
        for (int j = 0; j < 8; j++) {
            int p = pg * 8 + j;
            int ne = n0 + 2 * p, no = ne + 1;
#pragma unroll
            for (int o = 0; o < 4; o++) {
                int f = og * 4 + o;
                float ev, dv;
                unpack2(acc[o * 8 + j], ev, dv);
                if (ne < NN) {
                    int gg = sGid[2 * p];
                    atomicAdd(&SQ[gg * 64 + f], ev);
                    atomicAdd(&SQ[GG * HH + gg * 64 + f], ev * ev);
                }
                if (no < NN) {
                    int gg = sGid[2 * p + 1];
                    atomicAdd(&SQ[gg * 64 + f], dv);
                    atomicAdd(&SQ[GG * HH + gg * 64 + f], dv * dv);
                }
            }
        }
    }
}

// ================= fused encoder (dual branch, fp16 output) =================
#define ENC_SMEM ((8192 + 128 * PADT + 256) * 4)

__global__ void __launch_bounds__(128, 3) k_encoder(
    const float* __restrict__ x,
    const float* __restrict__ lW1, const float* __restrict__ lb1,
    const float* __restrict__ lW2, const float* __restrict__ lb2,
    const float* __restrict__ pW1, const float* __restrict__ pb1,
    const float* __restrict__ pW2, const float* __restrict__ pb2,
    __half* __restrict__ hout)
{
    extern __shared__ float smem[];
    float* sWreg = smem;
    float* sT    = smem + 8192;
    float* sB    = smem + 8192 + 128 * PADT;

    const int tid = threadIdx.x;
    const int n0 = blockIdx.x * 128;
    const int node = n0 + tid;
    const bool valid = node < NN;

    float* sWl1 = sWreg;
    float* sWp1 = sWreg + 2624;
    for (int i = tid; i < 656; i += 128) {
        ((float4*)sWl1)[i] = __ldg(((const float4*)lW1) + i);
        ((float4*)sWp1)[i] = __ldg(((const float4*)pW1) + i);
    }
    if (tid < HH) {
        sB[tid] = __ldg(&lb1[tid]); sB[64 + tid] = __ldg(&pb1[tid]);
        sB[128 + tid] = __ldg(&lb2[tid]); sB[192 + tid] = __ldg(&pb2[tid]);
    }
    for (int c = tid; c < 128 * IN_CH; c += 128) {
        int n = c / IN_CH, k = c - n * IN_CH;
        sT[n * PADT + k] = (n0 + n < NN) ? __ldg(&x[(size_t)(n0 + n) * IN_CH + k]) : 0.f;
    }
    __syncthreads();

    float* trow = sT + tid * PADT;
    float s = 0.f;
#pragma unroll
    for (int k = ATOM; k < IN_CH; k++) s += fabsf(trow[k]);
    const bool prot = s > 1e-6f;
    const float* sW1 = prot ? sWp1 : sWl1;
    const float* b1 = prot ? (sB + 64) : sB;
    const float* b2 = prot ? (sB + 192) : (sB + 128);

    unsigned long long acc[32];
#pragma unroll
    for (int j = 0; j < 32; j++) acc[j] = pack2(b1[2 * j], b1[2 * j + 1]);
    for (int k = 0; k < IN_CH; k++) {
        float zv = trow[k];
        kstep(sW1 + k * HH, pack2(zv, zv), acc);
    }
    float tv[HH];
#pragma unroll
    for (int j = 0; j < 32; j++) {
        float lo, hi; unpack2(acc[j], lo, hi);
        tv[2 * j] = fmaxf(lo, 0.f);
        tv[2 * j + 1] = fmaxf(hi, 0.f);
    }
    __syncthreads();

    float* sWl2 = sWreg;
    float* sWp2 = sWreg + 4096;
    for (int i = tid; i < 1024; i += 128) {
        ((float4*)sWl2)[i] = __ldg(((const float4*)lW2) + i);
        ((float4*)sWp2)[i] = __ldg(((const float4*)pW2) + i);
    }
#pragma unroll
    for (int j = 0; j < HH; j++) trow[j] = tv[j];
    __syncthreads();

    const float* sW2 = prot ? sWp2 : sWl2;
#pragma unroll
    for (int j = 0; j < 32; j++) acc[j] = pack2(b2[2 * j], b2[2 * j + 1]);
    for (int k = 0; k < HH; k++) {
        float zv = trow[k];
        kstep(sW2 + k * HH, pack2(zv, zv), acc);
    }
    if (valid) {
        uint4* op = (uint4*)(hout + (size_t)node * HH);
#pragma unroll
        for (int q = 0; q < 8; q++) {
            float f[8];
#pragma unroll
            for (int j = 0; j < 4; j++) {
                float lo, hi;
                unpack2(acc[q * 4 + j], lo, hi);
                f[2 * j] = fmaxf(lo, 0.f);
                f[2 * j + 1] = fmaxf(hi, 0.f);
            }
            uint4 v;
            v.x = f2h2(f[0], f[1]);
            v.y = f2h2(f[2], f[3]);
            v.z = f2h2(f[4], f[5]);
            v.w = f2h2(f[6], f[7]);
            op[q] = v;
        }
    }
}

__global__ void k_counts(const int* __restrict__ batch, float* __restrict__ cnt)
{
    int g = blockIdx.x * blockDim.x + threadIdx.x;
    if (g >= GG) return;
    int a = lower_bound_dev(batch, NN, g);
    int b = lower_bound_dev(batch, NN, g + 1);
    int c = b - a;
    cnt[g] = (float)(c > 0 ? c : 1);
}

// coef: consume SQ, then zero it for the next layer / next replay
__global__ void __launch_bounds__(256) k_coef(
    float* __restrict__ SQ, const float* __restrict__ cnt,
    const float* __restrict__ w, const float* __restrict__ b,
    const float* __restrict__ alpha, float* __restrict__ coef)
{
    int idx = blockIdx.x * 256 + threadIdx.x;
    int g = idx >> 6, f = idx & 63;
    float c = __ldg(&cnt[g]);
    float S = SQ[idx];
    float Q = SQ[GG * HH + idx];
    SQ[idx] = 0.f;
    SQ[GG * HH + idx] = 0.f;
    float m = S / c;
    float m2 = Q / c;
    float a = __ldg(&alpha[f]);
    float var = m2 - m * m * a * (2.0f - a);
    float rstd = rsqrtf(var + EPSN);
    float wf = __ldg(&w[f]);
    coef[idx] = wf * rstd;
    coef[GG * HH + idx] = __ldg(&b[f]) - wf * rstd * a * m;
}

// apply + relu, write fp16
__global__ void __launch_bounds__(256) k_apply(
    const float* __restrict__ h2, const int* __restrict__ batch,
    const float* __restrict__ coef, __half* __restrict__ hout)
{
    int idx = blockIdx.x * 256 + threadIdx.x;
    if (idx >= NN * 16) return;
    int node = idx >> 4, q = idx & 15;
    int g = __ldg(&batch[node]);
    float4 v = __ldg(((const float4*)h2) + idx);
    float4 c1 = __ldg(((const float4*)coef) + g * 16 + q);
    float4 c2 = __ldg(((const float4*)(coef + GG * HH)) + g * 16 + q);
    float o0 = fmaxf(fmaf(c1.x, v.x, c2.x), 0.f);
    float o1 = fmaxf(fmaf(c1.y, v.y, c2.y), 0.f);
    float o2 = fmaxf(fmaf(c1.z, v.z, c2.z), 0.f);
    float o3 = fmaxf(fmaf(c1.w, v.w, c2.w), 0.f);
    uint2 u;
    u.x = f2h2(o0, o1);
    u.y = f2h2(o2, o3);
    *(uint2*)(hout + (size_t)node * HH + q * 4) = u;
}

__global__ void __launch_bounds__(128) k_readout(
    const __half* __restrict__ h, const int* __restrict__ batch,
    const float* __restrict__ W1, const float* __restrict__ b1,
    const float* __restrict__ W2, const float* __restrict__ b2,
    float* __restrict__ out)
{
    const int g = blockIdx.x;
    const int tid = threadIdx.x;
    __shared__ int sRange[2];
    if (tid < 2) sRange[tid] = lower_bound_dev(batch, NN, g + tid);
    __syncthreads();
    const int start = sRange[0], end = sRange[1];

    const int f2 = (tid & 31) * 2;
    const int slot = tid >> 5;
    float s0 = 0.f, s1 = 0.f;
    for (int i = start + slot; i < end; i += 4) {
        unsigned int u = __ldg((const unsigned int*)(h + (size_t)i * HH + f2));
        float2 v = h2f2(u);
        s0 += v.x; s1 += v.y;
    }

    __shared__ float sp[256];
    __shared__ float pool[HH];
    __shared__ float tvs[HH];
    sp[tid * 2] = s0;
    sp[tid * 2 + 1] = s1;
    __syncthreads();
    if (tid < HH) {
        float acc = 0.f;
#pragma unroll
        for (int sl = 0; sl < 4; sl++)
            acc += sp[(sl * 32 + (tid >> 1)) * 2 + (tid & 1)];
        pool[tid] = acc;
    }
    __syncthreads();
    if (tid < HH) {
        float acc = __ldg(&b1[tid]);
#pragma unroll
        for (int k = 0; k < HH; k++)
            acc = fmaf(pool[k], __ldg(&W1[k * HH + tid]), acc);
        tvs[tid] = fmaxf(acc, 0.f) * __ldg(&W2[tid]);
    }
    __syncthreads();
    if (tid == 0) {
        float r = __ldg(b2);
#pragma unroll
        for (int k = 0; k < HH; k++) r += tvs[k];
        out[g] = r;
    }
}

// ================= launch ====================================================
extern "C" void kernel_launch(void* const* d_in, const int* in_sizes, int n_in,
                              void* d_out, int out_size)
{
    const float* x       = (const float*)d_in[0];
    const int*   ei      = (const int*)d_in[1];
    const float* ea      = (const float*)d_in[2];
    const int*   batch   = (const int*)d_in[3];
    const float* lig_W1  = (const float*)d_in[4];
    const float* lig_b1  = (const float*)d_in[5];
    const float* lig_W2  = (const float*)d_in[6];
    const float* lig_b2  = (const float*)d_in[7];
    const float* prot_W1 = (const float*)d_in[8];
    const float* prot_b1 = (const float*)d_in[9];
    const float* prot_W2 = (const float*)d_in[10];
    const float* prot_b2 = (const float*)d_in[11];
    const float* conv_We = (const float*)d_in[12];
    const float* conv_be = (const float*)d_in[13];
    const float* conv_W1 = (const float*)d_in[14];
    const float* conv_b1 = (const float*)d_in[15];
    const float* conv_W2 = (const float*)d_in[16];
    const float* conv_b2 = (const float*)d_in[17];
    const float* norm_w  = (const float*)d_in[18];
    const float* norm_b  = (const float*)d_in[19];
    const float* norm_a  = (const float*)d_in[20];
    const float* out_W1  = (const float*)d_in[21];
    const float* out_b1  = (const float*)d_in[22];
    const float* out_W2  = (const float*)d_in[23];
    const float* out_b2  = (const float*)d_in[24];
    float* out = (float*)d_out;

    const int* src = ei;
    const int* dst = ei + EE;

    void *phh, *ph2, *pag, *psq, *pcoef, *pcnt;
    void *pdeg, *poff, *pcur, *pbsum, *pcsrc, *peacsr;
    cudaGetSymbolAddress(&phh,  g_hh);
    cudaGetSymbolAddress(&ph2,  g_h2buf);
    cudaGetSymbolAddress(&pag,  g_aggrbuf);
    cudaGetSymbolAddress(&psq,  g_SQ);
    cudaGetSymbolAddress(&pcoef, g_coef);
    cudaGetSymbolAddress(&pcnt, g_cnt);
    cudaGetSymbolAddress(&pdeg, g_deg);
    cudaGetSymbolAddress(&poff, g_off);
    cudaGetSymbolAddress(&pcur, g_cur);
    cudaGetSymbolAddress(&pbsum, g_bsum);
    cudaGetSymbolAddress(&pcsrc, g_csrc);
    cudaGetSymbolAddress(&peacsr, g_eacsr);
    __half* h   = (__half*)phh;
    float* h2   = (float*)ph2;
    float* aggr = (float*)pag;
    float* SQ   = (float*)psq;
    float* coef = (float*)pcoef;
    float* cnt  = (float*)pcnt;
    int* deg  = (int*)pdeg;
    int* off  = (int*)poff;
    int* cur  = (int*)pcur;
    int* bsum = (int*)pbsum;
    int* csrc = (int*)pcsrc;
    float4* eacsr = (float4*)peacsr;

    static cudaStream_t s2 = nullptr;
    static cudaEvent_t evFork = nullptr, evJoin = nullptr;
    static bool attr_done = false;
    if (!attr_done) {
        cudaFuncSetAttribute(k_mlp, cudaFuncAttributeMaxDynamicSharedMemorySize, MLP_SMEM);
        cudaFuncSetAttribute(k_encoder, cudaFuncAttributeMaxDynamicSharedMemorySize, ENC_SMEM);
        cudaStreamCreateWithFlags(&s2, cudaStreamNonBlocking);
        cudaEventCreateWithFlags(&evFork, cudaEventDisableTiming);
        cudaEventCreateWithFlags(&evJoin, cudaEventDisableTiming);
        attr_done = true;
    }

    const int nodeBlocks = (NN + 127) / 128;        // 782
    const int gatherBlocks = (NN + 15) / 16;        // 6250
    const int edgeThreadBlocks = (EE + 255) / 256;  // 6250
    const int applyBlocks = (NN * 16 + 255) / 256;

    // ---- fork: CSR build on s2, encoder on main stream ----
    cudaEventRecord(evFork, 0);
    cudaStreamWaitEvent(s2, evFork, 0);

    cudaMemsetAsync(deg, 0, NN * sizeof(int), s2);
    k_hist<<<edgeThreadBlocks, 256, 0, s2>>>(dst, deg);
    k_scanblk<<<SCAN_NBLK, SCAN_BLK, 0, s2>>>(deg, off, bsum);
    k_scantop<<<1, 32, 0, s2>>>(bsum);
    k_scanadd<<<(NN + 255) / 256, 256, 0, s2>>>(off, bsum, cur);
    k_scatter<<<edgeThreadBlocks, 256, 0, s2>>>(src, dst, ea, cur, csrc, eacsr);
    cudaEventRecord(evJoin, s2);

    k_counts<<<1, 256>>>(batch, cnt);
    k_encoder<<<nodeBlocks, 128, ENC_SMEM>>>(x, lig_W1, lig_b1, lig_W2, lig_b2,
                                             prot_W1, prot_b1, prot_W2, prot_b2, h);

    cudaStreamWaitEvent(0, evJoin, 0);

    for (int l = 0; l < LL; l++) {
        k_gather<<<gatherBlocks, 256>>>(h, off, csrc, eacsr,
                                        conv_We + l * ED * HH, conv_be + l * HH, aggr);
        k_mlp<<<nodeBlocks, 128, MLP_SMEM>>>(h, aggr, batch,
                                             conv_W1 + l * HH * HH, conv_b1 + l * HH,
                                             conv_W2 + l * HH * HH, conv_b2 + l * HH,
                                             h2, SQ);
        k_coef<<<GG * HH / 256, 256>>>(SQ, cnt, norm_w + l * HH, norm_b + l * HH,
                                       norm_a + l * HH, coef);
        k_apply<<<applyBlocks, 256>>>(h2, batch, coef, h);
    }

    k_readout<<<GG, 128>>>(h, batch, out_W1, out_b1, out_W2, out_b2, out);
}